// round 12
// baseline (speedup 1.0000x reference)
#include <cuda_runtime.h>
#include <cuda_fp16.h>
#include <math.h>

#define NTOT   32768
#define CDIM   256
#define KCODES 1024
#define HW     1024
#define CHW    (CDIM*HW)
#define MT     128
#define MTS    64
#define THETA  0.2f
#define QP     257

// ---- output layout (flattened tuple, float32) ----
#define O_Q      0ull
#define O_LOSS   8388608ull
#define O_PERP   8388609ull
#define O_TOK    8388610ull
#define O_NCS    8421378ull
#define O_NEW_W  8422402ull   // == 2 mod 4: no float4 stores on out here
#define O_NEW_E  8684546ull

// ---- device scratch ----
__device__ __align__(16) __half g_zh[NTOT*CDIM];     // z fp16 [n][c]
__device__ __align__(16) __half g_eh[KCODES*CDIM];   // emb fp16 [k][c]
__device__ __align__(16) float g_eTf[CDIM*KCODES];   // fp32 transposed [c][k]
__device__ __align__(16) float g_enorm[KCODES];
__device__ __align__(16) float g_counts[KCODES];
__device__ __align__(16) float g_dw[KCODES*CDIM];
__device__ __align__(16) float g_invcs[KCODES];
__device__ int   g_idx[NTOT];
__device__ int   g_fixlist[NTOT];
__device__ int   g_nfix;
__device__ float g_loss;
__device__ int   g_cnt_i[KCODES];
__device__ int   g_off[KCODES];
__device__ int   g_cur[KCODES];
__device__ int   g_bucket[NTOT];

// ================= PTX helpers (all compute_80-safe) =================
__device__ __forceinline__ unsigned s2u(const void* p) {
    unsigned a;
    asm("{ .reg .u64 t; cvta.to.shared.u64 t, %1; cvt.u32.u64 %0, t; }"
        : "=r"(a) : "l"(p));
    return a;
}
#define CP16(d, s) \
    asm volatile("cp.async.cg.shared.global [%0], [%1], 16;" :: "r"(d), "l"(s))
#define CPCOMMIT() asm volatile("cp.async.commit_group;" ::: "memory")
#define CPWAIT1()  asm volatile("cp.async.wait_group 1;" ::: "memory")
#define CPWAIT0()  asm volatile("cp.async.wait_group 0;" ::: "memory")

__device__ __forceinline__ void ldsm4(unsigned& r0, unsigned& r1,
                                      unsigned& r2, unsigned& r3, unsigned a) {
    asm volatile("ldmatrix.sync.aligned.m8n8.x4.shared.b16 {%0,%1,%2,%3}, [%4];"
                 : "=r"(r0), "=r"(r1), "=r"(r2), "=r"(r3) : "r"(a));
}
__device__ __forceinline__ void mma_f16(float* c, const unsigned* a,
                                        unsigned b0, unsigned b1) {
    asm volatile(
        "mma.sync.aligned.m16n8k16.row.col.f32.f16.f16.f32 "
        "{%0,%1,%2,%3}, {%4,%5,%6,%7}, {%8,%9}, {%0,%1,%2,%3};"
        : "+f"(c[0]), "+f"(c[1]), "+f"(c[2]), "+f"(c[3])
        : "r"(a[0]), "r"(a[1]), "r"(a[2]), "r"(a[3]), "r"(b0), "r"(b1));
}

// GEMM smem layout (bytes)
#define A_BASE 0
#define B_BASE 65536
#define SM_EN  98304
#define SM_RED 102400
#define SM_TOT 108544

// ============================================================
// K0 (fused): blocks 0-255 zconv, 256-1279 prep, 1280-1283 zero
// ============================================================
__global__ __launch_bounds__(256) void vq_pre(const float* __restrict__ z_e,
                                              const float* __restrict__ emb) {
    const int blk = blockIdx.x, tid = threadIdx.x;
    if (blk < 256) {
        __shared__ float zs[32 * 130];
        int n0 = blk * MT;
        int b = n0 >> 10, hw0 = n0 & 1023;
        const float* zin = z_e + (size_t)b * CHW + hw0;
        int nn = tid & 127, ch = tid >> 7;
        int r = tid >> 1, half = tid & 1;
        for (int c0 = 0; c0 < CDIM; c0 += 32) {
            __syncthreads();
            #pragma unroll 4
            for (int i = 0; i < 16; i++) {
                int cl = ch + 2 * i;
                zs[cl * 130 + nn] = zin[(size_t)(c0 + cl) * HW + nn];
            }
            __syncthreads();
            uint4 hv[2];
            __half* hp = (__half*)hv;
            #pragma unroll
            for (int j = 0; j < 16; j++)
                hp[j] = __float2half(zs[(half * 16 + j) * 130 + r]);
            size_t base = (size_t)(n0 + r) * CDIM + c0 + half * 16;
            *(uint4*)&g_zh[base]     = hv[0];
            *(uint4*)&g_zh[base + 8] = hv[1];
        }
    } else if (blk < 1280) {
        __shared__ float red[8];
        int k = blk - 256;
        float v = emb[k * CDIM + tid];
        g_eh[k * CDIM + tid] = __float2half(v);
        g_eTf[(size_t)tid * KCODES + k] = v;
        float s = v * v;
        #pragma unroll
        for (int o = 16; o; o >>= 1) s += __shfl_xor_sync(~0u, s, o);
        if ((tid & 31) == 0) red[tid >> 5] = s;
        __syncthreads();
        if (tid == 0) {
            float tot = 0.f;
            #pragma unroll
            for (int i = 0; i < 8; i++) tot += red[i];
            g_enorm[k] = tot;
        }
    } else {
        int i = (blk - 1280) * 256 + tid;
        g_cnt_i[i] = 0;
        if (i == 0) { g_loss = 0.f; g_nfix = 0; }
    }
}

// ============================================================
// K1: single fp16 HMMA distance GEMM + top-2 + margin. 256 x 256
// ============================================================
__global__ __launch_bounds__(256, 2) void vq_gemm() {
    extern __shared__ char sm[];
    unsigned smb = s2u(sm);
    const int tid = threadIdx.x, lane = tid & 31, warp = tid >> 5;
    const int warpM = warp >> 2, warpN = warp & 3;
    const int n0 = blockIdx.x * MT;

    const uint4* zh4 = (const uint4*)g_zh;
    const uint4* eh4 = (const uint4*)g_eh;

    const int g = lane >> 3, gl = lane & 7;
    const unsigned colsel = (unsigned)((g >> 1) << 4);
    unsigned aoff[4], axor[4], boff[2], bxor[2];
    #pragma unroll
    for (int fm = 0; fm < 4; fm++) {
        int rr = warpM * 64 + fm * 16 + (g & 1) * 8 + gl;
        aoff[fm] = rr * 128; axor[fm] = (rr & 7) << 4;
    }
    #pragma unroll
    for (int f2 = 0; f2 < 2; f2++) {
        int rr = warpN * 32 + f2 * 16 + (g & 1) * 8 + gl;
        boff[f2] = rr * 128; bxor[f2] = (rr & 7) << 4;
    }

    auto issueB = [&](int it) {
        int nc = it >> 2, kc = it & 3, buf = it & 1;
        unsigned base = smb + B_BASE + buf * 16384;
        int k8 = kc << 3;
        #pragma unroll
        for (int p = 0; p < 4; p++) {
            int id = tid + p * 256;
            int rr = id >> 3, c8 = id & 7;
            unsigned sw = (unsigned)(rr * 128) + (unsigned)((c8 * 16) ^ ((rr & 7) << 4));
            CP16(base + sw, eh4 + (size_t)(nc * 128 + rr) * 32 + k8 + c8);
        }
    };

    #pragma unroll
    for (int kc = 0; kc < 4; kc++) {
        #pragma unroll
        for (int p = 0; p < 4; p++) {
            int id = tid + p * 256;
            int rr = id >> 3, c8 = id & 7;
            unsigned sw = (unsigned)(rr * 128) + (unsigned)((c8 * 16) ^ ((rr & 7) << 4));
            CP16(smb + A_BASE + kc * 16384 + sw,
                 zh4 + (size_t)(n0 + rr) * 32 + (kc << 3) + c8);
        }
    }
    CP16(smb + SM_EN + tid * 16, ((const uint4*)g_enorm) + tid);
    issueB(0);
    CPCOMMIT();
    issueB(1); CPCOMMIT();

    float v1[8], v2[8]; int i1[8];
    #pragma unroll
    for (int r = 0; r < 8; r++) { v1[r] = 3.4e38f; v2[r] = 3.4e38f; i1[r] = 0; }

    float acc[4][4][4];
    float* en_s = (float*)(sm + SM_EN);

#define UPD(r, sv, kk) { float _s = (sv); \
    if (_s < v1[r]) { v2[r] = v1[r]; v1[r] = _s; i1[r] = (kk); } \
    else if (_s < v2[r]) v2[r] = _s; }

    for (int it = 0; it < 32; it++) {
        const int kc = it & 3, nc = it >> 2, buf = it & 1;
        if (it < 31) CPWAIT1(); else CPWAIT0();
        __syncthreads();
        const unsigned bb  = smb + B_BASE + buf * 16384;
        const unsigned ab  = smb + A_BASE + kc * 16384;
        if (kc == 0) {
            #pragma unroll
            for (int fm = 0; fm < 4; fm++)
                #pragma unroll
                for (int fn = 0; fn < 4; fn++)
                    #pragma unroll
                    for (int q = 0; q < 4; q++) acc[fm][fn][q] = 0.f;
        }
        #pragma unroll
        for (int ks = 0; ks < 4; ks++) {
            const unsigned cb = (unsigned)(ks << 5) + colsel;
            unsigned ah[4][4], bh[2][4];
            #pragma unroll
            for (int fm = 0; fm < 4; fm++)
                ldsm4(ah[fm][0], ah[fm][1], ah[fm][2], ah[fm][3],
                      ab + aoff[fm] + (cb ^ axor[fm]));
            #pragma unroll
            for (int f2 = 0; f2 < 2; f2++)
                ldsm4(bh[f2][0], bh[f2][1], bh[f2][2], bh[f2][3],
                      bb + boff[f2] + (cb ^ bxor[f2]));
            #pragma unroll
            for (int fm = 0; fm < 4; fm++)
                #pragma unroll
                for (int fn = 0; fn < 4; fn++)
                    mma_f16(acc[fm][fn], ah[fm],
                            bh[fn >> 1][fn & 1], bh[fn >> 1][(fn & 1) + 2]);
        }
        if (kc == 3) {
            const int kbase = nc * 128 + warpN * 32 + (lane & 3) * 2;
            #pragma unroll
            for (int fn = 0; fn < 4; fn++) {
                float e0 = en_s[kbase + fn * 8];
                float e1 = en_s[kbase + fn * 8 + 1];
                #pragma unroll
                for (int fm = 0; fm < 4; fm++) {
                    UPD(fm * 2,     e0 - 2.f * acc[fm][fn][0], kbase + fn * 8);
                    UPD(fm * 2,     e1 - 2.f * acc[fm][fn][1], kbase + fn * 8 + 1);
                    UPD(fm * 2 + 1, e0 - 2.f * acc[fm][fn][2], kbase + fn * 8);
                    UPD(fm * 2 + 1, e1 - 2.f * acc[fm][fn][3], kbase + fn * 8 + 1);
                }
            }
        }
        __syncthreads();
        if (it + 2 < 32) { issueB(it + 2); CPCOMMIT(); }
    }

    #pragma unroll
    for (int r = 0; r < 8; r++) {
        #pragma unroll
        for (int off = 1; off <= 2; off <<= 1) {
            float v1o = __shfl_xor_sync(~0u, v1[r], off);
            int   i1o = __shfl_xor_sync(~0u, i1[r], off);
            float v2o = __shfl_xor_sync(~0u, v2[r], off);
            if (v1o < v1[r]) { v2[r] = fminf(v1[r], v2o); v1[r] = v1o; i1[r] = i1o; }
            else             { v2[r] = fminf(v2[r], v1o); }
        }
    }
    float* sv1 = (float*)(sm + SM_RED);
    int*   si1 = (int*)  (sm + SM_RED + 2048);
    float* sv2 = (float*)(sm + SM_RED + 4096);
    if ((lane & 3) == 0) {
        #pragma unroll
        for (int r = 0; r < 8; r++) {
            int mrow = warpM * 64 + (r >> 1) * 16 + (r & 1) * 8 + (lane >> 2);
            sv1[mrow * 4 + warpN] = v1[r];
            si1[mrow * 4 + warpN] = i1[r];
            sv2[mrow * 4 + warpN] = v2[r];
        }
    }
    __syncthreads();
    if (tid < MT) {
        float b1 = sv1[tid * 4], b2 = sv2[tid * 4];
        int   bi = si1[tid * 4];
        #pragma unroll
        for (int w = 1; w < 4; w++) {
            float a1 = sv1[tid * 4 + w], a2 = sv2[tid * 4 + w];
            int   ai = si1[tid * 4 + w];
            if (a1 < b1) { b2 = fminf(b1, a2); b1 = a1; bi = ai; }
            else         { b2 = fminf(b2, a1); }
        }
        int n = n0 + tid;
        g_idx[n] = bi;
        if (b2 - b1 < THETA) {
            int p = atomicAdd(&g_nfix, 1);
            g_fixlist[p] = n;
        }
    }
}

// ============================================================
// K2: exact fp32 rescore, coalesced via g_eTf, 8 rows batched.
// ============================================================
__global__ __launch_bounds__(1024) void vq_fix(const float* __restrict__ z_e) {
    __shared__ float zrow[8][CDIM];
    __shared__ float rv[32];
    __shared__ int   ri[32];
    const int tid = threadIdx.x, lane = tid & 31, warp = tid >> 5;
    const int nfix = g_nfix;
    for (int base = blockIdx.x * 8; base < nfix; base += gridDim.x * 8) {
        const int cnt = min(8, nfix - base);
        #pragma unroll
        for (int pass = 0; pass < 2; pass++) {
            int j = (tid >> 8) + pass * 4;
            int c = tid & 255;
            if (j < cnt) {
                int n = g_fixlist[base + j];
                int b = n >> 10, hw = n & 1023;
                zrow[j][c] = z_e[(size_t)b * CHW + (size_t)c * HW + hw];
            }
        }
        __syncthreads();

        float s[8];
        #pragma unroll
        for (int j = 0; j < 8; j++) s[j] = 0.f;
        #pragma unroll 8
        for (int c = 0; c < CDIM; c++) {
            float e = g_eTf[(size_t)c * KCODES + tid];
            #pragma unroll
            for (int j = 0; j < 8; j++) s[j] += zrow[j][c] * e;
        }
        float en = g_enorm[tid];

        for (int j = 0; j < cnt; j++) {
            float v = en - 2.0f * s[j];
            int   ix = tid;
            #pragma unroll
            for (int o = 16; o; o >>= 1) {
                float vo = __shfl_xor_sync(~0u, v, o);
                int   io = __shfl_xor_sync(~0u, ix, o);
                if (vo < v || (vo == v && io < ix)) { v = vo; ix = io; }
            }
            if (lane == 0) { rv[warp] = v; ri[warp] = ix; }
            __syncthreads();
            if (tid < 32) {
                float vv = rv[tid]; int ii = ri[tid];
                #pragma unroll
                for (int o = 16; o; o >>= 1) {
                    float vo = __shfl_xor_sync(~0u, vv, o);
                    int   io = __shfl_xor_sync(~0u, ii, o);
                    if (vo < vv || (vo == vv && io < ii)) { vv = vo; ii = io; }
                }
                if (tid == 0) g_idx[g_fixlist[base + j]] = ii;
            }
            __syncthreads();
        }
    }
}

// ============================================================
// K3: q_out only (smem-staged, coalesced).  512 x 256, 3 CTA/SM
// ============================================================
__global__ __launch_bounds__(256, 3) void vq_qout(const float* __restrict__ emb,
                                                  float* __restrict__ out) {
    extern __shared__ float qs[];   // [64][QP]
    __shared__ int idx_s[MTS];
    int tid = threadIdx.x, warp = tid >> 5, lane = tid & 31;
    int n0 = blockIdx.x * MTS;
    int b = n0 >> 10, hw0 = n0 & 1023;

    if (tid < MTS) idx_s[tid] = g_idx[n0 + tid];
    __syncthreads();

    for (int r = warp; r < MTS; r += 8) {
        const float* er = emb + (size_t)idx_s[r] * CDIM;
        float* qr = qs + r * QP;
        #pragma unroll
        for (int c = lane; c < CDIM; c += 32) qr[c] = er[c];
    }
    __syncthreads();

    int nn = tid & 63, ch = tid >> 6;
    float* ob = out + O_Q + (size_t)b * CHW + hw0 + nn;
    #pragma unroll 4
    for (int i = 0; i < 64; i++) {
        int c = ch + 4 * i;
        ob[(size_t)c * HW] = qs[nn * QP + c];
    }
}

// ============================================================
// K4a: tokens out + histogram.  32 x 1024
// ============================================================
__global__ void vq_hist(float* __restrict__ out) {
    int n = blockIdx.x * 1024 + threadIdx.x;
    int ix = g_idx[n];
    out[O_TOK + n] = (float)ix;
    atomicAdd(&g_cnt_i[ix], 1);
}

// ============================================================
// K4b: prefix sum -> offsets, cursors, float counts.  1 x 1024
// ============================================================
__global__ void vq_offs() {
    __shared__ int s[1024];
    int t = threadIdx.x;
    int c = g_cnt_i[t];
    s[t] = c;
    __syncthreads();
    for (int off = 1; off < 1024; off <<= 1) {
        int v = (t >= off) ? s[t - off] : 0;
        __syncthreads();
        s[t] += v;
        __syncthreads();
    }
    int excl = s[t] - c;
    g_off[t] = excl;
    g_cur[t] = excl;
    g_counts[t] = (float)c;
}

// ============================================================
// K4c: bucket fill (inverted index).  32 x 1024
// ============================================================
__global__ void vq_bucket() {
    int n = blockIdx.x * 1024 + threadIdx.x;
    int ix = g_idx[n];
    int pos = atomicAdd(&g_cur[ix], 1);
    g_bucket[pos] = n;
}

// ============================================================
// K4d: per-code dw + loss (gather, NO atomics on dw). 1024 x 256
// ============================================================
__global__ __launch_bounds__(256) void vq_dw(const float* __restrict__ emb) {
    __shared__ int   sn[256];
    __shared__ float lred[8];
    const int k = blockIdx.x, c = threadIdx.x;
    const int lane = c & 31, warp = c >> 5;
    const float e = emb[k * CDIM + c];
    const int off = g_off[k], cnt = g_cnt_i[k];
    float acc = 0.f, lacc = 0.f;
    for (int base = 0; base < cnt; base += 256) {
        int m = min(256, cnt - base);
        if (c < m) sn[c] = g_bucket[off + base + c];
        __syncthreads();
        for (int j = 0; j < m; j++) {
            float z = __half2float(g_zh[(size_t)sn[j] * CDIM + c]);
            acc += z;
            float d = e - z;
            lacc += d * d;
        }
        __syncthreads();
    }
    g_dw[(size_t)k * CDIM + c] = acc;
    #pragma unroll
    for (int o = 16; o; o >>= 1) lacc += __shfl_xor_sync(~0u, lacc, o);
    if (lane == 0) lred[warp] = lacc;
    __syncthreads();
    if (c == 0) {
        float s = 0.f;
        #pragma unroll
        for (int i = 0; i < 8; i++) s += lred[i];
        atomicAdd(&g_loss, s);
    }
}

// ============================================================
// K5: cluster-size EMA + loss/perplexity.  1 x 1024
// ============================================================
__global__ void vq_final_a(const float* __restrict__ ema_cs,
                           float* __restrict__ out) {
    int t = threadIdx.x;
    __shared__ float s1[32], s2[32];
    float cnt = g_counts[t];
    float ncs = ema_cs[t] * 0.99f + 0.01f * cnt;
    out[O_NCS + t] = ncs;
    float p  = cnt * (1.0f / 32768.0f);
    float pl = p * logf(p + 1e-10f);
    float a = ncs, bsum = pl;
    #pragma unroll
    for (int o = 16; o; o >>= 1) {
        a += __shfl_xor_sync(~0u, a, o);
        bsum += __shfl_xor_sync(~0u, bsum, o);
    }
    if ((t & 31) == 0) { s1[t >> 5] = a; s2[t >> 5] = bsum; }
    __syncthreads();
    if (t < 32) {
        float a2 = s1[t], b2 = s2[t];
        #pragma unroll
        for (int o = 16; o; o >>= 1) {
            a2 += __shfl_xor_sync(~0u, a2, o);
            b2 += __shfl_xor_sync(~0u, b2, o);
        }
        if (t == 0) { s1[0] = a2; s2[0] = b2; }
    }
    __syncthreads();
    float nsum = s1[0];
    if (t == 0) {
        out[O_PERP] = expf(-s2[0]);
        out[O_LOSS] = 0.25f * g_loss * (1.0f / 8388608.0f);
    }
    float cs = (ncs + 1e-10f) / (nsum + 1024.0f * 1e-10f) * nsum;
    g_invcs[t] = 1.0f / cs;
}

// ============================================================
// K6: new_ema_w + new_embedding.  256 x 256
// ============================================================
__global__ void vq_final_b(const float* __restrict__ ema_w,
                           float* __restrict__ out) {
    int i = (blockIdx.x * 256 + threadIdx.x) * 4;
    float4 w  = *(const float4*)&ema_w[i];
    float4 dw = *(const float4*)&g_dw[i];
    float4 nw;
    nw.x = w.x * 0.99f + 0.01f * dw.x;
    nw.y = w.y * 0.99f + 0.01f * dw.y;
    nw.z = w.z * 0.99f + 0.01f * dw.z;
    nw.w = w.w * 0.99f + 0.01f * dw.w;
    float2 a = {nw.x, nw.y}, c = {nw.z, nw.w};
    *(float2*)&out[O_NEW_W + i]     = a;
    *(float2*)&out[O_NEW_W + i + 2] = c;
    float ic = g_invcs[i >> 8];
    float2 e0 = {nw.x * ic, nw.y * ic}, e1 = {nw.z * ic, nw.w * ic};
    *(float2*)&out[O_NEW_E + i]     = e0;
    *(float2*)&out[O_NEW_E + i + 2] = e1;
}

// ============================================================
extern "C" void kernel_launch(void* const* d_in, const int* in_sizes, int n_in,
                              void* d_out, int out_size) {
    const float* z_e    = (const float*)d_in[0];
    const float* emb    = (const float*)d_in[1];
    const float* ema_cs = (const float*)d_in[2];
    const float* ema_w  = (const float*)d_in[3];
    float* out = (float*)d_out;

    cudaFuncSetAttribute(vq_gemm, cudaFuncAttributeMaxDynamicSharedMemorySize,
                         SM_TOT);
    cudaFuncSetAttribute(vq_qout, cudaFuncAttributeMaxDynamicSharedMemorySize,
                         MTS * QP * 4);

    vq_pre<<<1284, 256>>>(z_e, emb);                    // 1
    vq_gemm<<<NTOT / MT, 256, SM_TOT>>>();              // 2
    vq_fix<<<256, 1024>>>(z_e);                         // 3
    vq_qout<<<NTOT / MTS, 256, MTS * QP * 4>>>(emb, out); // 4 <- profiled slot
    vq_hist<<<32, 1024>>>(out);                         // 5
    vq_offs<<<1, 1024>>>();                             // 6
    vq_bucket<<<32, 1024>>>();                          // 7
    vq_dw<<<KCODES, 256>>>(emb);                        // 8
    vq_final_a<<<1, 1024>>>(ema_cs, out);               // 9
    vq_final_b<<<256, 256>>>(ema_w, out);               // 10
}

// round 13
// speedup vs baseline: 1.0022x; 1.0022x over previous
#include <cuda_runtime.h>
#include <cuda_fp16.h>
#include <math.h>

#define NTOT   32768
#define CDIM   256
#define KCODES 1024
#define HW     1024
#define CHW    (CDIM*HW)
#define MT     128
#define MTS    64
#define THETA  0.2f
#define QP     257
#define DWCHUNK 2048

// ---- output layout (flattened tuple, float32) ----
#define O_Q      0ull
#define O_LOSS   8388608ull
#define O_PERP   8388609ull
#define O_TOK    8388610ull
#define O_NCS    8421378ull
#define O_NEW_W  8422402ull   // == 2 mod 4: no float4 stores on out here
#define O_NEW_E  8684546ull

// ---- device scratch ----
__device__ __align__(16) __half g_zh[NTOT*CDIM];     // z fp16 [n][c]
__device__ __align__(16) __half g_eh[KCODES*CDIM];   // emb fp16 [k][c]
__device__ __align__(16) float g_eTf[CDIM*KCODES];   // fp32 transposed [c][k]
__device__ __align__(16) float g_enorm[KCODES];
__device__ __align__(16) float g_counts[KCODES];
__device__ __align__(16) float g_dw[KCODES*CDIM];
__device__ __align__(16) float g_invcs[KCODES];
__device__ int   g_idx[NTOT];
__device__ int   g_fixlist[NTOT];
__device__ int   g_nfix;
__device__ float g_loss;

// ================= PTX helpers (all compute_80-safe) =================
__device__ __forceinline__ unsigned s2u(const void* p) {
    unsigned a;
    asm("{ .reg .u64 t; cvta.to.shared.u64 t, %1; cvt.u32.u64 %0, t; }"
        : "=r"(a) : "l"(p));
    return a;
}
#define CP16(d, s) \
    asm volatile("cp.async.cg.shared.global [%0], [%1], 16;" :: "r"(d), "l"(s))
#define CPCOMMIT() asm volatile("cp.async.commit_group;" ::: "memory")
#define CPWAIT1()  asm volatile("cp.async.wait_group 1;" ::: "memory")
#define CPWAIT0()  asm volatile("cp.async.wait_group 0;" ::: "memory")

__device__ __forceinline__ void ldsm4(unsigned& r0, unsigned& r1,
                                      unsigned& r2, unsigned& r3, unsigned a) {
    asm volatile("ldmatrix.sync.aligned.m8n8.x4.shared.b16 {%0,%1,%2,%3}, [%4];"
                 : "=r"(r0), "=r"(r1), "=r"(r2), "=r"(r3) : "r"(a));
}
__device__ __forceinline__ void mma_f16(float* c, const unsigned* a,
                                        unsigned b0, unsigned b1) {
    asm volatile(
        "mma.sync.aligned.m16n8k16.row.col.f32.f16.f16.f32 "
        "{%0,%1,%2,%3}, {%4,%5,%6,%7}, {%8,%9}, {%0,%1,%2,%3};"
        : "+f"(c[0]), "+f"(c[1]), "+f"(c[2]), "+f"(c[3])
        : "r"(a[0]), "r"(a[1]), "r"(a[2]), "r"(a[3]), "r"(b0), "r"(b1));
}

// GEMM smem layout (bytes)
#define A_BASE 0
#define B_BASE 65536
#define SM_EN  98304
#define SM_RED 102400
#define SM_TOT 108544

// ============================================================
// K0 (fused): blocks 0-255 zconv, 256-1279 prep, 1280 zero
// ============================================================
__global__ __launch_bounds__(256) void vq_pre(const float* __restrict__ z_e,
                                              const float* __restrict__ emb) {
    const int blk = blockIdx.x, tid = threadIdx.x;
    if (blk < 256) {
        __shared__ float zs[32 * 130];
        int n0 = blk * MT;
        int b = n0 >> 10, hw0 = n0 & 1023;
        const float* zin = z_e + (size_t)b * CHW + hw0;
        int nn = tid & 127, ch = tid >> 7;
        int r = tid >> 1, half = tid & 1;
        for (int c0 = 0; c0 < CDIM; c0 += 32) {
            __syncthreads();
            #pragma unroll 4
            for (int i = 0; i < 16; i++) {
                int cl = ch + 2 * i;
                zs[cl * 130 + nn] = zin[(size_t)(c0 + cl) * HW + nn];
            }
            __syncthreads();
            uint4 hv[2];
            __half* hp = (__half*)hv;
            #pragma unroll
            for (int j = 0; j < 16; j++)
                hp[j] = __float2half(zs[(half * 16 + j) * 130 + r]);
            size_t base = (size_t)(n0 + r) * CDIM + c0 + half * 16;
            *(uint4*)&g_zh[base]     = hv[0];
            *(uint4*)&g_zh[base + 8] = hv[1];
        }
    } else if (blk < 1280) {
        __shared__ float red[8];
        int k = blk - 256;
        float v = emb[k * CDIM + tid];
        g_eh[k * CDIM + tid] = __float2half(v);
        g_eTf[(size_t)tid * KCODES + k] = v;
        float s = v * v;
        #pragma unroll
        for (int o = 16; o; o >>= 1) s += __shfl_xor_sync(~0u, s, o);
        if ((tid & 31) == 0) red[tid >> 5] = s;
        __syncthreads();
        if (tid == 0) {
            float tot = 0.f;
            #pragma unroll
            for (int i = 0; i < 8; i++) tot += red[i];
            g_enorm[k] = tot;
        }
    } else {
        if (tid == 0) { g_loss = 0.f; g_nfix = 0; }
    }
}

// ============================================================
// K1: single fp16 HMMA distance GEMM + top-2 + margin. 256 x 256
// ============================================================
__global__ __launch_bounds__(256, 2) void vq_gemm() {
    extern __shared__ char sm[];
    unsigned smb = s2u(sm);
    const int tid = threadIdx.x, lane = tid & 31, warp = tid >> 5;
    const int warpM = warp >> 2, warpN = warp & 3;
    const int n0 = blockIdx.x * MT;

    const uint4* zh4 = (const uint4*)g_zh;
    const uint4* eh4 = (const uint4*)g_eh;

    const int g = lane >> 3, gl = lane & 7;
    const unsigned colsel = (unsigned)((g >> 1) << 4);
    unsigned aoff[4], axor[4], boff[2], bxor[2];
    #pragma unroll
    for (int fm = 0; fm < 4; fm++) {
        int rr = warpM * 64 + fm * 16 + (g & 1) * 8 + gl;
        aoff[fm] = rr * 128; axor[fm] = (rr & 7) << 4;
    }
    #pragma unroll
    for (int f2 = 0; f2 < 2; f2++) {
        int rr = warpN * 32 + f2 * 16 + (g & 1) * 8 + gl;
        boff[f2] = rr * 128; bxor[f2] = (rr & 7) << 4;
    }

    auto issueB = [&](int it) {
        int nc = it >> 2, kc = it & 3, buf = it & 1;
        unsigned base = smb + B_BASE + buf * 16384;
        int k8 = kc << 3;
        #pragma unroll
        for (int p = 0; p < 4; p++) {
            int id = tid + p * 256;
            int rr = id >> 3, c8 = id & 7;
            unsigned sw = (unsigned)(rr * 128) + (unsigned)((c8 * 16) ^ ((rr & 7) << 4));
            CP16(base + sw, eh4 + (size_t)(nc * 128 + rr) * 32 + k8 + c8);
        }
    };

    #pragma unroll
    for (int kc = 0; kc < 4; kc++) {
        #pragma unroll
        for (int p = 0; p < 4; p++) {
            int id = tid + p * 256;
            int rr = id >> 3, c8 = id & 7;
            unsigned sw = (unsigned)(rr * 128) + (unsigned)((c8 * 16) ^ ((rr & 7) << 4));
            CP16(smb + A_BASE + kc * 16384 + sw,
                 zh4 + (size_t)(n0 + rr) * 32 + (kc << 3) + c8);
        }
    }
    CP16(smb + SM_EN + tid * 16, ((const uint4*)g_enorm) + tid);
    issueB(0);
    CPCOMMIT();
    issueB(1); CPCOMMIT();

    float v1[8], v2[8]; int i1[8];
    #pragma unroll
    for (int r = 0; r < 8; r++) { v1[r] = 3.4e38f; v2[r] = 3.4e38f; i1[r] = 0; }

    float acc[4][4][4];
    float* en_s = (float*)(sm + SM_EN);

#define UPD(r, sv, kk) { float _s = (sv); \
    if (_s < v1[r]) { v2[r] = v1[r]; v1[r] = _s; i1[r] = (kk); } \
    else if (_s < v2[r]) v2[r] = _s; }

    for (int it = 0; it < 32; it++) {
        const int kc = it & 3, nc = it >> 2, buf = it & 1;
        if (it < 31) CPWAIT1(); else CPWAIT0();
        __syncthreads();
        const unsigned bb  = smb + B_BASE + buf * 16384;
        const unsigned ab  = smb + A_BASE + kc * 16384;
        if (kc == 0) {
            #pragma unroll
            for (int fm = 0; fm < 4; fm++)
                #pragma unroll
                for (int fn = 0; fn < 4; fn++)
                    #pragma unroll
                    for (int q = 0; q < 4; q++) acc[fm][fn][q] = 0.f;
        }
        #pragma unroll
        for (int ks = 0; ks < 4; ks++) {
            const unsigned cb = (unsigned)(ks << 5) + colsel;
            unsigned ah[4][4], bh[2][4];
            #pragma unroll
            for (int fm = 0; fm < 4; fm++)
                ldsm4(ah[fm][0], ah[fm][1], ah[fm][2], ah[fm][3],
                      ab + aoff[fm] + (cb ^ axor[fm]));
            #pragma unroll
            for (int f2 = 0; f2 < 2; f2++)
                ldsm4(bh[f2][0], bh[f2][1], bh[f2][2], bh[f2][3],
                      bb + boff[f2] + (cb ^ bxor[f2]));
            #pragma unroll
            for (int fm = 0; fm < 4; fm++)
                #pragma unroll
                for (int fn = 0; fn < 4; fn++)
                    mma_f16(acc[fm][fn], ah[fm],
                            bh[fn >> 1][fn & 1], bh[fn >> 1][(fn & 1) + 2]);
        }
        if (kc == 3) {
            const int kbase = nc * 128 + warpN * 32 + (lane & 3) * 2;
            #pragma unroll
            for (int fn = 0; fn < 4; fn++) {
                float e0 = en_s[kbase + fn * 8];
                float e1 = en_s[kbase + fn * 8 + 1];
                #pragma unroll
                for (int fm = 0; fm < 4; fm++) {
                    UPD(fm * 2,     e0 - 2.f * acc[fm][fn][0], kbase + fn * 8);
                    UPD(fm * 2,     e1 - 2.f * acc[fm][fn][1], kbase + fn * 8 + 1);
                    UPD(fm * 2 + 1, e0 - 2.f * acc[fm][fn][2], kbase + fn * 8);
                    UPD(fm * 2 + 1, e1 - 2.f * acc[fm][fn][3], kbase + fn * 8 + 1);
                }
            }
        }
        __syncthreads();
        if (it + 2 < 32) { issueB(it + 2); CPCOMMIT(); }
    }

    #pragma unroll
    for (int r = 0; r < 8; r++) {
        #pragma unroll
        for (int off = 1; off <= 2; off <<= 1) {
            float v1o = __shfl_xor_sync(~0u, v1[r], off);
            int   i1o = __shfl_xor_sync(~0u, i1[r], off);
            float v2o = __shfl_xor_sync(~0u, v2[r], off);
            if (v1o < v1[r]) { v2[r] = fminf(v1[r], v2o); v1[r] = v1o; i1[r] = i1o; }
            else             { v2[r] = fminf(v2[r], v1o); }
        }
    }
    float* sv1 = (float*)(sm + SM_RED);
    int*   si1 = (int*)  (sm + SM_RED + 2048);
    float* sv2 = (float*)(sm + SM_RED + 4096);
    if ((lane & 3) == 0) {
        #pragma unroll
        for (int r = 0; r < 8; r++) {
            int mrow = warpM * 64 + (r >> 1) * 16 + (r & 1) * 8 + (lane >> 2);
            sv1[mrow * 4 + warpN] = v1[r];
            si1[mrow * 4 + warpN] = i1[r];
            sv2[mrow * 4 + warpN] = v2[r];
        }
    }
    __syncthreads();
    if (tid < MT) {
        float b1 = sv1[tid * 4], b2 = sv2[tid * 4];
        int   bi = si1[tid * 4];
        #pragma unroll
        for (int w = 1; w < 4; w++) {
            float a1 = sv1[tid * 4 + w], a2 = sv2[tid * 4 + w];
            int   ai = si1[tid * 4 + w];
            if (a1 < b1) { b2 = fminf(b1, a2); b1 = a1; bi = ai; }
            else         { b2 = fminf(b2, a1); }
        }
        int n = n0 + tid;
        g_idx[n] = bi;
        if (b2 - b1 < THETA) {
            int p = atomicAdd(&g_nfix, 1);
            g_fixlist[p] = n;
        }
    }
}

// ============================================================
// K2: exact fp32 rescore, coalesced via g_eTf, 8 rows batched.
// ============================================================
__global__ __launch_bounds__(1024) void vq_fix(const float* __restrict__ z_e) {
    __shared__ float zrow[8][CDIM];
    __shared__ float rv[32];
    __shared__ int   ri[32];
    const int tid = threadIdx.x, lane = tid & 31, warp = tid >> 5;
    const int nfix = g_nfix;
    for (int base = blockIdx.x * 8; base < nfix; base += gridDim.x * 8) {
        const int cnt = min(8, nfix - base);
        #pragma unroll
        for (int pass = 0; pass < 2; pass++) {
            int j = (tid >> 8) + pass * 4;
            int c = tid & 255;
            if (j < cnt) {
                int n = g_fixlist[base + j];
                int b = n >> 10, hw = n & 1023;
                zrow[j][c] = z_e[(size_t)b * CHW + (size_t)c * HW + hw];
            }
        }
        __syncthreads();

        float s[8];
        #pragma unroll
        for (int j = 0; j < 8; j++) s[j] = 0.f;
        #pragma unroll 8
        for (int c = 0; c < CDIM; c++) {
            float e = g_eTf[(size_t)c * KCODES + tid];
            #pragma unroll
            for (int j = 0; j < 8; j++) s[j] += zrow[j][c] * e;
        }
        float en = g_enorm[tid];

        for (int j = 0; j < cnt; j++) {
            float v = en - 2.0f * s[j];
            int   ix = tid;
            #pragma unroll
            for (int o = 16; o; o >>= 1) {
                float vo = __shfl_xor_sync(~0u, v, o);
                int   io = __shfl_xor_sync(~0u, ix, o);
                if (vo < v || (vo == v && io < ix)) { v = vo; ix = io; }
            }
            if (lane == 0) { rv[warp] = v; ri[warp] = ix; }
            __syncthreads();
            if (tid < 32) {
                float vv = rv[tid]; int ii = ri[tid];
                #pragma unroll
                for (int o = 16; o; o >>= 1) {
                    float vo = __shfl_xor_sync(~0u, vv, o);
                    int   io = __shfl_xor_sync(~0u, ii, o);
                    if (vo < vv || (vo == vv && io < ii)) { vv = vo; ii = io; }
                }
                if (tid == 0) g_idx[g_fixlist[base + j]] = ii;
            }
            __syncthreads();
        }
    }
}

// ============================================================
// K3: q_out + tokens (smem-staged, coalesced). 512 x 256, 3 CTA/SM
// ============================================================
__global__ __launch_bounds__(256, 3) void vq_qout(const float* __restrict__ emb,
                                                  float* __restrict__ out) {
    extern __shared__ float qs[];   // [64][QP]
    __shared__ int idx_s[MTS];
    int tid = threadIdx.x, warp = tid >> 5, lane = tid & 31;
    int n0 = blockIdx.x * MTS;
    int b = n0 >> 10, hw0 = n0 & 1023;

    if (tid < MTS) {
        int ix = g_idx[n0 + tid];
        idx_s[tid] = ix;
        out[O_TOK + n0 + tid] = (float)ix;
    }
    __syncthreads();

    for (int r = warp; r < MTS; r += 8) {
        const float* er = emb + (size_t)idx_s[r] * CDIM;
        float* qr = qs + r * QP;
        #pragma unroll
        for (int c = lane; c < CDIM; c += 32) qr[c] = er[c];
    }
    __syncthreads();

    int nn = tid & 63, ch = tid >> 6;
    float* ob = out + O_Q + (size_t)b * CHW + hw0 + nn;
    #pragma unroll 4
    for (int i = 0; i < 64; i++) {
        int c = ch + 4 * i;
        ob[(size_t)c * HW] = qs[nn * QP + c];
    }
}

// ============================================================
// K4: per-code dw + counts + loss via self-scan of L2-resident
// g_idx (chunked, overflow-safe). 1024 x 256. No float atomics.
// ============================================================
__global__ __launch_bounds__(256) void vq_dw(const float* __restrict__ emb) {
    __shared__ int   rows[DWCHUNK];
    __shared__ int   s_cnt;
    __shared__ float lred[8];
    const int k = blockIdx.x, c = threadIdx.x;
    const int lane = c & 31, warp = c >> 5;
    const float e = emb[k * CDIM + c];
    float acc = 0.f, lacc = 0.f;
    int total = 0;

    for (int base = 0; base < NTOT; base += DWCHUNK) {
        if (c == 0) s_cnt = 0;
        __syncthreads();
        #pragma unroll
        for (int p = 0; p < DWCHUNK / 256; p++) {
            int i = base + p * 256 + c;
            if (g_idx[i] == k) { int q = atomicAdd(&s_cnt, 1); rows[q] = i; }
        }
        __syncthreads();
        int m = s_cnt;
        for (int j = 0; j < m; j++) {
            float z = __half2float(g_zh[(size_t)rows[j] * CDIM + c]);
            acc += z;
            float d = e - z;
            lacc += d * d;
        }
        total += m;
        __syncthreads();
    }

    g_dw[(size_t)k * CDIM + c] = acc;
    if (c == 0) g_counts[k] = (float)total;
    #pragma unroll
    for (int o = 16; o; o >>= 1) lacc += __shfl_xor_sync(~0u, lacc, o);
    if (lane == 0) lred[warp] = lacc;
    __syncthreads();
    if (c == 0) {
        float s = 0.f;
        #pragma unroll
        for (int i = 0; i < 8; i++) s += lred[i];
        atomicAdd(&g_loss, s);
    }
}

// ============================================================
// K5: cluster-size EMA + loss/perplexity.  1 x 1024
// ============================================================
__global__ void vq_final_a(const float* __restrict__ ema_cs,
                           float* __restrict__ out) {
    int t = threadIdx.x;
    __shared__ float s1[32], s2[32];
    float cnt = g_counts[t];
    float ncs = ema_cs[t] * 0.99f + 0.01f * cnt;
    out[O_NCS + t] = ncs;
    float p  = cnt * (1.0f / 32768.0f);
    float pl = p * logf(p + 1e-10f);
    float a = ncs, bsum = pl;
    #pragma unroll
    for (int o = 16; o; o >>= 1) {
        a += __shfl_xor_sync(~0u, a, o);
        bsum += __shfl_xor_sync(~0u, bsum, o);
    }
    if ((t & 31) == 0) { s1[t >> 5] = a; s2[t >> 5] = bsum; }
    __syncthreads();
    if (t < 32) {
        float a2 = s1[t], b2 = s2[t];
        #pragma unroll
        for (int o = 16; o; o >>= 1) {
            a2 += __shfl_xor_sync(~0u, a2, o);
            b2 += __shfl_xor_sync(~0u, b2, o);
        }
        if (t == 0) { s1[0] = a2; s2[0] = b2; }
    }
    __syncthreads();
    float nsum = s1[0];
    if (t == 0) {
        out[O_PERP] = expf(-s2[0]);
        out[O_LOSS] = 0.25f * g_loss * (1.0f / 8388608.0f);
    }
    float cs = (ncs + 1e-10f) / (nsum + 1024.0f * 1e-10f) * nsum;
    g_invcs[t] = 1.0f / cs;
}

// ============================================================
// K6: new_ema_w + new_embedding.  256 x 256
// ============================================================
__global__ void vq_final_b(const float* __restrict__ ema_w,
                           float* __restrict__ out) {
    int i = (blockIdx.x * 256 + threadIdx.x) * 4;
    float4 w  = *(const float4*)&ema_w[i];
    float4 dw = *(const float4*)&g_dw[i];
    float4 nw;
    nw.x = w.x * 0.99f + 0.01f * dw.x;
    nw.y = w.y * 0.99f + 0.01f * dw.y;
    nw.z = w.z * 0.99f + 0.01f * dw.z;
    nw.w = w.w * 0.99f + 0.01f * dw.w;
    float2 a = {nw.x, nw.y}, c = {nw.z, nw.w};
    *(float2*)&out[O_NEW_W + i]     = a;
    *(float2*)&out[O_NEW_W + i + 2] = c;
    float ic = g_invcs[i >> 8];
    float2 e0 = {nw.x * ic, nw.y * ic}, e1 = {nw.z * ic, nw.w * ic};
    *(float2*)&out[O_NEW_E + i]     = e0;
    *(float2*)&out[O_NEW_E + i + 2] = e1;
}

// ============================================================
extern "C" void kernel_launch(void* const* d_in, const int* in_sizes, int n_in,
                              void* d_out, int out_size) {
    const float* z_e    = (const float*)d_in[0];
    const float* emb    = (const float*)d_in[1];
    const float* ema_cs = (const float*)d_in[2];
    const float* ema_w  = (const float*)d_in[3];
    float* out = (float*)d_out;

    cudaFuncSetAttribute(vq_gemm, cudaFuncAttributeMaxDynamicSharedMemorySize,
                         SM_TOT);
    cudaFuncSetAttribute(vq_qout, cudaFuncAttributeMaxDynamicSharedMemorySize,
                         MTS * QP * 4);

    vq_pre<<<1281, 256>>>(z_e, emb);                      // 1
    vq_gemm<<<NTOT / MT, 256, SM_TOT>>>();                // 2
    vq_fix<<<256, 1024>>>(z_e);                           // 3
    vq_qout<<<NTOT / MTS, 256, MTS * QP * 4>>>(emb, out); // 4 <- profiled slot
    vq_dw<<<KCODES, 256>>>(emb);                          // 5
    vq_final_a<<<1, 1024>>>(ema_cs, out);                 // 6
    vq_final_b<<<256, 256>>>(ema_w, out);                 // 7
}

// round 14
// speedup vs baseline: 1.3478x; 1.3449x over previous
#include <cuda_runtime.h>
#include <cuda_fp16.h>
#include <math.h>

#define NTOT   32768
#define CDIM   256
#define KCODES 1024
#define HW     1024
#define CHW    (CDIM*HW)
#define MT     128
#define THETA  0.2f
#define QP     257
#define FLAGB  0x40000000

// ---- output layout (flattened tuple, float32) ----
#define O_Q      0ull
#define O_LOSS   8388608ull
#define O_PERP   8388609ull
#define O_TOK    8388610ull
#define O_NCS    8421378ull
#define O_NEW_W  8422402ull   // == 2 mod 4: no float4 stores on out here
#define O_NEW_E  8684546ull

// ---- device scratch ----
__device__ __align__(16) __half g_zh[NTOT*CDIM];     // z fp16 [n][c]
__device__ __align__(16) __half g_eh[KCODES*CDIM];   // emb fp16 [k][c]
__device__ __align__(16) float g_eTf[CDIM*KCODES];   // fp32 transposed [c][k]
__device__ __align__(16) float g_enorm[KCODES];
__device__ __align__(16) float g_counts[KCODES];
__device__ __align__(16) float g_dw[KCODES*CDIM];
__device__ __align__(16) float g_invcs[KCODES];
__device__ int   g_fixlist[NTOT];
__device__ int   g_nfix;
__device__ float g_loss;

// ================= PTX helpers (all compute_80-safe) =================
__device__ __forceinline__ unsigned s2u(const void* p) {
    unsigned a;
    asm("{ .reg .u64 t; cvta.to.shared.u64 t, %1; cvt.u32.u64 %0, t; }"
        : "=r"(a) : "l"(p));
    return a;
}
#define CP16(d, s) \
    asm volatile("cp.async.cg.shared.global [%0], [%1], 16;" :: "r"(d), "l"(s))
#define CPCOMMIT() asm volatile("cp.async.commit_group;" ::: "memory")
#define CPWAIT1()  asm volatile("cp.async.wait_group 1;" ::: "memory")
#define CPWAIT0()  asm volatile("cp.async.wait_group 0;" ::: "memory")

__device__ __forceinline__ void ldsm4(unsigned& r0, unsigned& r1,
                                      unsigned& r2, unsigned& r3, unsigned a) {
    asm volatile("ldmatrix.sync.aligned.m8n8.x4.shared.b16 {%0,%1,%2,%3}, [%4];"
                 : "=r"(r0), "=r"(r1), "=r"(r2), "=r"(r3) : "r"(a));
}
__device__ __forceinline__ void mma_f16(float* c, const unsigned* a,
                                        unsigned b0, unsigned b1) {
    asm volatile(
        "mma.sync.aligned.m16n8k16.row.col.f32.f16.f16.f32 "
        "{%0,%1,%2,%3}, {%4,%5,%6,%7}, {%8,%9}, {%0,%1,%2,%3};"
        : "+f"(c[0]), "+f"(c[1]), "+f"(c[2]), "+f"(c[3])
        : "r"(a[0]), "r"(a[1]), "r"(a[2]), "r"(a[3]), "r"(b0), "r"(b1));
}

// GEMM smem layout (bytes)
#define A_BASE 0
#define B_BASE 65536
#define SM_EN  98304
#define SM_RED 102400
#define SM_TOT 108544

// ============================================================
// K0 (fused): 0-255 zconv, 256-1279 prep, 1280-1535 zero dw/etc
// ============================================================
__global__ __launch_bounds__(256) void vq_pre(const float* __restrict__ z_e,
                                              const float* __restrict__ emb) {
    const int blk = blockIdx.x, tid = threadIdx.x;
    if (blk < 256) {
        __shared__ float zs[32 * 130];
        int n0 = blk * MT;
        int b = n0 >> 10, hw0 = n0 & 1023;
        const float* zin = z_e + (size_t)b * CHW + hw0;
        int nn = tid & 127, ch = tid >> 7;
        int r = tid >> 1, half = tid & 1;
        for (int c0 = 0; c0 < CDIM; c0 += 32) {
            __syncthreads();
            #pragma unroll 4
            for (int i = 0; i < 16; i++) {
                int cl = ch + 2 * i;
                zs[cl * 130 + nn] = zin[(size_t)(c0 + cl) * HW + nn];
            }
            __syncthreads();
            uint4 hv[2];
            __half* hp = (__half*)hv;
            #pragma unroll
            for (int j = 0; j < 16; j++)
                hp[j] = __float2half(zs[(half * 16 + j) * 130 + r]);
            size_t base = (size_t)(n0 + r) * CDIM + c0 + half * 16;
            *(uint4*)&g_zh[base]     = hv[0];
            *(uint4*)&g_zh[base + 8] = hv[1];
        }
    } else if (blk < 1280) {
        __shared__ float red[8];
        int k = blk - 256;
        float v = emb[k * CDIM + tid];
        g_eh[k * CDIM + tid] = __float2half(v);
        g_eTf[(size_t)tid * KCODES + k] = v;
        float s = v * v;
        #pragma unroll
        for (int o = 16; o; o >>= 1) s += __shfl_xor_sync(~0u, s, o);
        if ((tid & 31) == 0) red[tid >> 5] = s;
        __syncthreads();
        if (tid == 0) {
            float tot = 0.f;
            #pragma unroll
            for (int i = 0; i < 8; i++) tot += red[i];
            g_enorm[k] = tot;
        }
    } else {
        int i = (blk - 1280) * 256 + tid;
        float4 z4 = {0.f, 0.f, 0.f, 0.f};
        *(float4*)&g_dw[(size_t)i * 4] = z4;
        if (i < KCODES) g_counts[i] = 0.f;
        if (i == 0) { g_loss = 0.f; g_nfix = 0; }
    }
}

// ============================================================
// K1: fp16 HMMA distance GEMM + top-2 + FUSED scatter epilogue.
// 256 x 256, 2 CTA/SM. Flagged rows handled by vq_fix.
// ============================================================
__global__ __launch_bounds__(256, 2) void vq_gemm(const float* __restrict__ emb,
                                                  float* __restrict__ out) {
    extern __shared__ char sm[];
    __shared__ int   fidx_s[MT];
    __shared__ float lred_s[8];
    unsigned smb = s2u(sm);
    const int tid = threadIdx.x, lane = tid & 31, warp = tid >> 5;
    const int warpM = warp >> 2, warpN = warp & 3;
    const int n0 = blockIdx.x * MT;

    const uint4* zh4 = (const uint4*)g_zh;
    const uint4* eh4 = (const uint4*)g_eh;

    const int g = lane >> 3, gl = lane & 7;
    const unsigned colsel = (unsigned)((g >> 1) << 4);
    unsigned aoff[4], axor[4], boff[2], bxor[2];
    #pragma unroll
    for (int fm = 0; fm < 4; fm++) {
        int rr = warpM * 64 + fm * 16 + (g & 1) * 8 + gl;
        aoff[fm] = rr * 128; axor[fm] = (rr & 7) << 4;
    }
    #pragma unroll
    for (int f2 = 0; f2 < 2; f2++) {
        int rr = warpN * 32 + f2 * 16 + (g & 1) * 8 + gl;
        boff[f2] = rr * 128; bxor[f2] = (rr & 7) << 4;
    }

    auto issueB = [&](int it) {
        int nc = it >> 2, kc = it & 3, buf = it & 1;
        unsigned base = smb + B_BASE + buf * 16384;
        int k8 = kc << 3;
        #pragma unroll
        for (int p = 0; p < 4; p++) {
            int id = tid + p * 256;
            int rr = id >> 3, c8 = id & 7;
            unsigned sw = (unsigned)(rr * 128) + (unsigned)((c8 * 16) ^ ((rr & 7) << 4));
            CP16(base + sw, eh4 + (size_t)(nc * 128 + rr) * 32 + k8 + c8);
        }
    };

    #pragma unroll
    for (int kc = 0; kc < 4; kc++) {
        #pragma unroll
        for (int p = 0; p < 4; p++) {
            int id = tid + p * 256;
            int rr = id >> 3, c8 = id & 7;
            unsigned sw = (unsigned)(rr * 128) + (unsigned)((c8 * 16) ^ ((rr & 7) << 4));
            CP16(smb + A_BASE + kc * 16384 + sw,
                 zh4 + (size_t)(n0 + rr) * 32 + (kc << 3) + c8);
        }
    }
    CP16(smb + SM_EN + tid * 16, ((const uint4*)g_enorm) + tid);
    issueB(0);
    CPCOMMIT();
    issueB(1); CPCOMMIT();

    float v1[8], v2[8]; int i1[8];
    #pragma unroll
    for (int r = 0; r < 8; r++) { v1[r] = 3.4e38f; v2[r] = 3.4e38f; i1[r] = 0; }

    float acc[4][4][4];
    float* en_s = (float*)(sm + SM_EN);

#define UPD(r, sv, kk) { float _s = (sv); \
    if (_s < v1[r]) { v2[r] = v1[r]; v1[r] = _s; i1[r] = (kk); } \
    else if (_s < v2[r]) v2[r] = _s; }

    for (int it = 0; it < 32; it++) {
        const int kc = it & 3, nc = it >> 2, buf = it & 1;
        if (it < 31) CPWAIT1(); else CPWAIT0();
        __syncthreads();
        const unsigned bb  = smb + B_BASE + buf * 16384;
        const unsigned ab  = smb + A_BASE + kc * 16384;
        if (kc == 0) {
            #pragma unroll
            for (int fm = 0; fm < 4; fm++)
                #pragma unroll
                for (int fn = 0; fn < 4; fn++)
                    #pragma unroll
                    for (int q = 0; q < 4; q++) acc[fm][fn][q] = 0.f;
        }
        #pragma unroll
        for (int ks = 0; ks < 4; ks++) {
            const unsigned cb = (unsigned)(ks << 5) + colsel;
            unsigned ah[4][4], bh[2][4];
            #pragma unroll
            for (int fm = 0; fm < 4; fm++)
                ldsm4(ah[fm][0], ah[fm][1], ah[fm][2], ah[fm][3],
                      ab + aoff[fm] + (cb ^ axor[fm]));
            #pragma unroll
            for (int f2 = 0; f2 < 2; f2++)
                ldsm4(bh[f2][0], bh[f2][1], bh[f2][2], bh[f2][3],
                      bb + boff[f2] + (cb ^ bxor[f2]));
            #pragma unroll
            for (int fm = 0; fm < 4; fm++)
                #pragma unroll
                for (int fn = 0; fn < 4; fn++)
                    mma_f16(acc[fm][fn], ah[fm],
                            bh[fn >> 1][fn & 1], bh[fn >> 1][(fn & 1) + 2]);
        }
        if (kc == 3) {
            const int kbase = nc * 128 + warpN * 32 + (lane & 3) * 2;
            #pragma unroll
            for (int fn = 0; fn < 4; fn++) {
                float e0 = en_s[kbase + fn * 8];
                float e1 = en_s[kbase + fn * 8 + 1];
                #pragma unroll
                for (int fm = 0; fm < 4; fm++) {
                    UPD(fm * 2,     e0 - 2.f * acc[fm][fn][0], kbase + fn * 8);
                    UPD(fm * 2,     e1 - 2.f * acc[fm][fn][1], kbase + fn * 8 + 1);
                    UPD(fm * 2 + 1, e0 - 2.f * acc[fm][fn][2], kbase + fn * 8);
                    UPD(fm * 2 + 1, e1 - 2.f * acc[fm][fn][3], kbase + fn * 8 + 1);
                }
            }
        }
        __syncthreads();
        if (it + 2 < 32) { issueB(it + 2); CPCOMMIT(); }
    }

    #pragma unroll
    for (int r = 0; r < 8; r++) {
        #pragma unroll
        for (int off = 1; off <= 2; off <<= 1) {
            float v1o = __shfl_xor_sync(~0u, v1[r], off);
            int   i1o = __shfl_xor_sync(~0u, i1[r], off);
            float v2o = __shfl_xor_sync(~0u, v2[r], off);
            if (v1o < v1[r]) { v2[r] = fminf(v1[r], v2o); v1[r] = v1o; i1[r] = i1o; }
            else             { v2[r] = fminf(v2[r], v1o); }
        }
    }
    float* sv1 = (float*)(sm + SM_RED);
    int*   si1 = (int*)  (sm + SM_RED + 2048);
    float* sv2 = (float*)(sm + SM_RED + 4096);
    if ((lane & 3) == 0) {
        #pragma unroll
        for (int r = 0; r < 8; r++) {
            int mrow = warpM * 64 + (r >> 1) * 16 + (r & 1) * 8 + (lane >> 2);
            sv1[mrow * 4 + warpN] = v1[r];
            si1[mrow * 4 + warpN] = i1[r];
            sv2[mrow * 4 + warpN] = v2[r];
        }
    }
    __syncthreads();
    if (tid < MT) {
        float b1 = sv1[tid * 4], b2 = sv2[tid * 4];
        int   bi = si1[tid * 4];
        #pragma unroll
        for (int w = 1; w < 4; w++) {
            float a1 = sv1[tid * 4 + w], a2 = sv2[tid * 4 + w];
            int   ai = si1[tid * 4 + w];
            if (a1 < b1) { b2 = fminf(b1, a2); b1 = a1; bi = ai; }
            else         { b2 = fminf(b2, a1); }
        }
        int n = n0 + tid;
        bool fl = (b2 - b1 < THETA);
        fidx_s[tid] = bi | (fl ? FLAGB : 0);
        if (fl) {
            int p = atomicAdd(&g_nfix, 1);
            g_fixlist[p] = n;
        } else {
            out[O_TOK + n] = (float)bi;
            atomicAdd(&g_counts[bi], 1.0f);
        }
    }
    __syncthreads();

    // ---- fused scatter epilogue (unflagged rows), reuse A/B smem ----
    float* qs = (float*)sm;     // 64 x QP fp32 = 65792 B (A + head of B)
    const int bB = n0 >> 10, hw0 = n0 & 1023;
    float lacc = 0.f;
    for (int h = 0; h < 2; h++) {
        const int rb = h * 64;
        for (int r = warp; r < 64; r += 8) {
            int ix = fidx_s[rb + r] & ~FLAGB;
            const float* er = emb + (size_t)ix * CDIM;
            float* qr = qs + r * QP;
            #pragma unroll
            for (int c = lane; c < CDIM; c += 32) qr[c] = er[c];
        }
        __syncthreads();
        {
            int nn = tid & 63, ch = tid >> 6;
            if (!(fidx_s[rb + nn] & FLAGB)) {
                float* ob = out + O_Q + (size_t)bB * CHW + hw0 + rb + nn;
                #pragma unroll 4
                for (int i = 0; i < 64; i++) {
                    int c = ch + 4 * i;
                    ob[(size_t)c * HW] = qs[nn * QP + c];
                }
            }
        }
        {
            const __half* zh = g_zh + (size_t)(n0 + rb) * CDIM;
            const int rofs = tid >> 7, c2 = tid & 127;
            for (int rp = 0; rp < 64; rp += 2) {
                int r = rp + rofs;
                int fi = fidx_s[rb + r];
                if (fi & FLAGB) continue;
                unsigned u = *(const unsigned*)&zh[(size_t)r * CDIM + c2 * 2];
                __half2 hh = *(__half2*)&u;
                float z0 = __low2float(hh), z1 = __high2float(hh);
                float q0 = qs[r * QP + c2 * 2], q1 = qs[r * QP + c2 * 2 + 1];
                float d0 = q0 - z0, d1 = q1 - z1;
                lacc += d0 * d0 + d1 * d1;
                float* dwr = g_dw + (size_t)(fi & ~FLAGB) * CDIM + c2 * 2;
                atomicAdd(dwr,     z0);
                atomicAdd(dwr + 1, z1);
            }
        }
        __syncthreads();
    }
    #pragma unroll
    for (int o = 16; o; o >>= 1) lacc += __shfl_xor_sync(~0u, lacc, o);
    if (lane == 0) lred_s[warp] = lacc;
    __syncthreads();
    if (tid == 0) {
        float s = 0.f;
        #pragma unroll
        for (int i = 0; i < 8; i++) s += lred_s[i];
        atomicAdd(&g_loss, s);
    }
}

// ============================================================
// K2: exact fp32 rescore of flagged rows + their full outputs
// (token, count, q_out, dw, loss).  256 x 1024
// ============================================================
__global__ __launch_bounds__(1024) void vq_fix(const float* __restrict__ z_e,
                                               const float* __restrict__ emb,
                                               float* __restrict__ out) {
    __shared__ float zrow[8][CDIM];
    __shared__ float rv[32];
    __shared__ int   ri[32];
    __shared__ int   s_ii;
    const int tid = threadIdx.x, lane = tid & 31, warp = tid >> 5;
    const int nfix = g_nfix;
    for (int base = blockIdx.x * 8; base < nfix; base += gridDim.x * 8) {
        const int cnt = min(8, nfix - base);
        #pragma unroll
        for (int pass = 0; pass < 2; pass++) {
            int j = (tid >> 8) + pass * 4;
            int c = tid & 255;
            if (j < cnt) {
                int n = g_fixlist[base + j];
                int b = n >> 10, hw = n & 1023;
                zrow[j][c] = z_e[(size_t)b * CHW + (size_t)c * HW + hw];
            }
        }
        __syncthreads();

        float s[8];
        #pragma unroll
        for (int j = 0; j < 8; j++) s[j] = 0.f;
        #pragma unroll 8
        for (int c = 0; c < CDIM; c++) {
            float e = g_eTf[(size_t)c * KCODES + tid];
            #pragma unroll
            for (int j = 0; j < 8; j++) s[j] += zrow[j][c] * e;
        }
        float en = g_enorm[tid];

        for (int j = 0; j < cnt; j++) {
            float v = en - 2.0f * s[j];
            int   ix = tid;
            #pragma unroll
            for (int o = 16; o; o >>= 1) {
                float vo = __shfl_xor_sync(~0u, v, o);
                int   io = __shfl_xor_sync(~0u, ix, o);
                if (vo < v || (vo == v && io < ix)) { v = vo; ix = io; }
            }
            if (lane == 0) { rv[warp] = v; ri[warp] = ix; }
            __syncthreads();
            if (tid < 32) {
                float vv = rv[tid]; int ii = ri[tid];
                #pragma unroll
                for (int o = 16; o; o >>= 1) {
                    float vo = __shfl_xor_sync(~0u, vv, o);
                    int   io = __shfl_xor_sync(~0u, ii, o);
                    if (vo < vv || (vo == vv && io < ii)) { vv = vo; ii = io; }
                }
                if (tid == 0) s_ii = ii;
            }
            __syncthreads();

            // ---- outputs for this flagged row ----
            const int ii = s_ii;
            const int n = g_fixlist[base + j];
            const int bb = n >> 10, hw = n & 1023;
            float l = 0.f;
            if (tid < CDIM) {
                float q = emb[(size_t)ii * CDIM + tid];
                float z = zrow[j][tid];
                float d = q - z;
                l = d * d;
                out[O_Q + (size_t)bb * CHW + (size_t)tid * HW + hw] = q;
                atomicAdd(&g_dw[(size_t)ii * CDIM + tid], z);
            }
            #pragma unroll
            for (int o = 16; o; o >>= 1) l += __shfl_xor_sync(~0u, l, o);
            __syncthreads();               // rv reads (above) fully done
            if (lane == 0) rv[warp] = l;
            __syncthreads();
            if (tid == 0) {
                float tot = 0.f;
                #pragma unroll
                for (int w = 0; w < 32; w++) tot += rv[w];
                out[O_TOK + n] = (float)ii;
                atomicAdd(&g_counts[ii], 1.0f);
                atomicAdd(&g_loss, tot);
            }
            __syncthreads();
        }
    }
}

// ============================================================
// K3: cluster-size EMA + loss/perplexity.  1 x 1024
// ============================================================
__global__ void vq_final_a(const float* __restrict__ ema_cs,
                           float* __restrict__ out) {
    int t = threadIdx.x;
    __shared__ float s1[32], s2[32];
    float cnt = g_counts[t];
    float ncs = ema_cs[t] * 0.99f + 0.01f * cnt;
    out[O_NCS + t] = ncs;
    float p  = cnt * (1.0f / 32768.0f);
    float pl = p * logf(p + 1e-10f);
    float a = ncs, bsum = pl;
    #pragma unroll
    for (int o = 16; o; o >>= 1) {
        a += __shfl_xor_sync(~0u, a, o);
        bsum += __shfl_xor_sync(~0u, bsum, o);
    }
    if ((t & 31) == 0) { s1[t >> 5] = a; s2[t >> 5] = bsum; }
    __syncthreads();
    if (t < 32) {
        float a2 = s1[t], b2 = s2[t];
        #pragma unroll
        for (int o = 16; o; o >>= 1) {
            a2 += __shfl_xor_sync(~0u, a2, o);
            b2 += __shfl_xor_sync(~0u, b2, o);
        }
        if (t == 0) { s1[0] = a2; s2[0] = b2; }
    }
    __syncthreads();
    float nsum = s1[0];
    if (t == 0) {
        out[O_PERP] = expf(-s2[0]);
        out[O_LOSS] = 0.25f * g_loss * (1.0f / 8388608.0f);
    }
    float cs = (ncs + 1e-10f) / (nsum + 1024.0f * 1e-10f) * nsum;
    g_invcs[t] = 1.0f / cs;
}

// ============================================================
// K4: new_ema_w + new_embedding.  256 x 256
// ============================================================
__global__ void vq_final_b(const float* __restrict__ ema_w,
                           float* __restrict__ out) {
    int i = (blockIdx.x * 256 + threadIdx.x) * 4;
    float4 w  = *(const float4*)&ema_w[i];
    float4 dw = *(const float4*)&g_dw[i];
    float4 nw;
    nw.x = w.x * 0.99f + 0.01f * dw.x;
    nw.y = w.y * 0.99f + 0.01f * dw.y;
    nw.z = w.z * 0.99f + 0.01f * dw.z;
    nw.w = w.w * 0.99f + 0.01f * dw.w;
    float2 a = {nw.x, nw.y}, c = {nw.z, nw.w};
    *(float2*)&out[O_NEW_W + i]     = a;
    *(float2*)&out[O_NEW_W + i + 2] = c;
    float ic = g_invcs[i >> 8];
    float2 e0 = {nw.x * ic, nw.y * ic}, e1 = {nw.z * ic, nw.w * ic};
    *(float2*)&out[O_NEW_E + i]     = e0;
    *(float2*)&out[O_NEW_E + i + 2] = e1;
}

// ============================================================
extern "C" void kernel_launch(void* const* d_in, const int* in_sizes, int n_in,
                              void* d_out, int out_size) {
    const float* z_e    = (const float*)d_in[0];
    const float* emb    = (const float*)d_in[1];
    const float* ema_cs = (const float*)d_in[2];
    const float* ema_w  = (const float*)d_in[3];
    float* out = (float*)d_out;

    cudaFuncSetAttribute(vq_gemm, cudaFuncAttributeMaxDynamicSharedMemorySize,
                         SM_TOT);

    vq_pre<<<1536, 256>>>(z_e, emb);                      // 1
    vq_gemm<<<NTOT / MT, 256, SM_TOT>>>(emb, out);        // 2
    vq_fix<<<256, 1024>>>(z_e, emb, out);                 // 3
    vq_final_a<<<1, 1024>>>(ema_cs, out);                 // 4
    vq_final_b<<<256, 256>>>(ema_w, out);                 // 5
}